// round 16
// baseline (speedup 1.0000x reference)
#include <cuda_runtime.h>
#include <cstdint>

// Problem constants (fixed by the reference setup_inputs)
constexpr int B = 256;
constexpr int T = 30000;
constexpr int C = 3;

constexpr int L = 1500;           // output chunk length; T/L = 20 chunks
constexpr int W = 292;            // warm-up steps; (L+W) = 1792 = 7*256 exactly
constexpr int NCHUNK = T / L;     // 20

constexpr float ALPHA = 0.939f;
constexpr float CFF   = 3.0f;
constexpr float EPS   = 1e-10f;

__host__ __device__ constexpr double dpow(double a, int n) {
    double v = 1.0;
    for (int i = 0; i < n; ++i) v *= a;
    return v;
}
__device__ constexpr float APJ[8] = {   // alpha^(j+1), j = 0..7
    (float)dpow(0.939, 1), (float)dpow(0.939, 2), (float)dpow(0.939, 3), (float)dpow(0.939, 4),
    (float)dpow(0.939, 5), (float)dpow(0.939, 6), (float)dpow(0.939, 7), (float)dpow(0.939, 8)
};
__device__ constexpr float SCOEF[5] = { // alpha^(8 * 2^st), st = 0..4
    (float)dpow(0.939, 8), (float)dpow(0.939, 16), (float)dpow(0.939, 32),
    (float)dpow(0.939, 64), (float)dpow(0.939, 128)
};

#define FULLMASK 0xffffffffu

// Per-warp smem tile: 32 rows x 32 words (4 KB), double buffered.
// Row r's slot s (s=0..5, float4 granularity) lives at word
//   r*32 + sigma_r(s)*4,   sigma_r(s) = ((s + 6r) & 7) ^ ((r>>2) & 1)
// Column-Latin over any 8 consecutive rows (row pattern conflict-free) AND
// any 8 consecutive tile-float4 indices G=6r+s hit 8 distinct bank groups
// (transposed pattern conflict-free). Verified by enumeration.
constexpr int WARP_TILE_W = 32 * 32;

__device__ __forceinline__ int sigma_word(int r, int s) {
    return r * 32 + ((((s + 6 * r) & 7) ^ ((r >> 2) & 1)) << 2);
}

__global__ __launch_bounds__(128)
void char_scan_kernel(const float* __restrict__ in, float* __restrict__ out) {
    __shared__ float sm_all[4][2][WARP_TILE_W];   // 4 warps x 2 tiles x 4KB = 32KB

    const int gwarp = (blockIdx.x * blockDim.x + threadIdx.x) >> 5;
    const int lane  = threadIdx.x & 31;
    if (gwarp >= B * NCHUNK) return;

    const int wip = threadIdx.x >> 5;
    float* const tile0 = &sm_all[wip][0][0];
    float* const tile1 = &sm_all[wip][1][0];
    const uint32_t smb0 = (uint32_t)__cvta_generic_to_shared(tile0);
    const uint32_t smb1 = (uint32_t)__cvta_generic_to_shared(tile1);

    const int b  = gwarp / NCHUNK;
    const int k  = gwarp % NCHUNK;
    const int t0 = k * L;                  // first stored timestep (mult of 4)
    const int ts = (k == 0) ? 0 : t0 - W;  // first scanned timestep (mult of 4)
    const int tend = t0 + L;               // exclusive store bound

    const float* __restrict__ base  = in  + (size_t)b * T * C;
    float* __restrict__       obase = out + (size_t)b * T * C;

    // ---- hoisted swizzled smem word-offsets (constant per lane) ----
    int offT[6];                           // transposed pattern: G = 32q + lane
    #pragma unroll
    for (int q = 0; q < 6; ++q) {
        const int G = q * 32 + lane;
        offT[q] = sigma_word(G / 6, G % 6);
    }
    int offR[6];                           // own-row pattern: r = lane
    #pragma unroll
    for (int s = 0; s < 6; ++s) offR[s] = sigma_word(lane, s);

    // cross-round carries
    float carry_d[3] = {0.f, 0.f, 0.f};
    float carry_r[3];
    if (ts == 0) {
        carry_r[0] = 0.f; carry_r[1] = 0.f; carry_r[2] = 0.f;
    } else {
        carry_r[0] = base[(size_t)(ts - 1) * 3 + 0];
        carry_r[1] = base[(size_t)(ts - 1) * 3 + 1];
        carry_r[2] = base[(size_t)(ts - 1) * 3 + 2];
    }

    const int nrounds = (tend - ts + 255) >> 8;   // 256 timesteps per round
    const int g0lo = t0 * 3;     // store-valid float range [g0lo, g0hi)
    const int g0hi = tend * 3;

    // ---- cp.async issue: global round rd -> swizzled tile (transposed write) ----
    auto issue = [&](int rd, uint32_t smb) {
        const int fb = (ts + rd * 256) * 3;       // mult of 4 -> 16B aligned
        const float* p = base + fb + lane * 4;
        #pragma unroll
        for (int q = 0; q < 6; ++q) {
            const uint32_t dst = smb + (uint32_t)offT[q] * 4u;
            const float* src = p + q * 128;
            asm volatile("cp.async.cg.shared.global [%0], [%1], 16;\n"
                         :: "r"(dst), "l"(src) : "memory");
        }
        asm volatile("cp.async.commit_group;\n" ::: "memory");
    };

    issue(0, smb0);   // prologue: prefetch round 0

    for (int rd = 0; rd < nrounds; ++rd) {
        const int tb = ts + rd * 256;
        const int fb = tb * 3;
        const bool more = (rd + 1 < nrounds);
        if (more) issue(rd + 1, ((rd + 1) & 1) ? smb1 : smb0);

        // wait for round rd's tile (allow the just-issued group to stay in flight)
        if (more) asm volatile("cp.async.wait_group 1;\n" ::: "memory");
        else      asm volatile("cp.async.wait_group 0;\n" ::: "memory");
        __syncwarp();   // cross-lane visibility of cp.async'd tile

        float* const sm = (rd & 1) ? tile1 : tile0;

        // ---- read own row: 24 floats = timesteps tb+8*lane..+7, ch-major ----
        float r[24];
        #pragma unroll
        for (int s = 0; s < 6; ++s) {
            float4 u = *reinterpret_cast<const float4*>(sm + offR[s]);
            r[s * 4 + 0] = u.x; r[s * 4 + 1] = u.y;
            r[s * 4 + 2] = u.z; r[s * 4 + 3] = u.w;
        }

        #pragma unroll
        for (int c = 0; c < 3; ++c) {
            float rp = __shfl_up_sync(FULLMASK, r[21 + c], 1);
            if (lane == 0) rp = carry_r[c];

            // local serial scan over 8 steps; lane 0 folds in carry_d
            float s[8];
            float u0 = (r[c] - rp) + EPS;
            s[0] = (lane == 0) ? fmaf(ALPHA, carry_d[c], u0) : u0;
            #pragma unroll
            for (int j = 1; j < 8; ++j) {
                float uj = (r[j * 3 + c] - r[(j - 1) * 3 + c]) + EPS;
                s[j] = fmaf(ALPHA, s[j - 1], uj);
            }

            // Kogge-Stone over lane aggregates, ratio alpha^8
            float p = s[7];
            #pragma unroll
            for (int st = 0; st < 5; ++st) {
                const int dlt = 1 << st;
                float tshf = __shfl_up_sync(FULLMASK, p, dlt);
                if (lane >= dlt) p = fmaf(SCOEF[st], tshf, p);
            }

            float inc = __shfl_up_sync(FULLMASK, p, 1);
            float dprev;
            if (lane == 0) { inc = 0.f; dprev = carry_d[c]; }
            else           { dprev = inc; }

            // carries for next round (read r before in-place overwrite)
            carry_d[c] = __shfl_sync(FULLMASK, p, 31);
            carry_r[c] = __shfl_sync(FULLMASK, r[21 + c], 31);

            // fixup + characteristic, overwriting r[] in place
            #pragma unroll
            for (int j = 0; j < 8; ++j) {
                float d    = fmaf(APJ[j], inc, s[j]);
                float diff = d - dprev;
                r[j * 3 + c] = fmaf(d, d, CFF * (diff * diff));
                dprev = d;
            }
        }

        // ---- output path (skipped entirely on pure warm-up rounds) ----
        const bool doStore = (tb + 256 > t0);    // warp-uniform
        if (doStore) {
            const bool needGuard = (tb < t0) || (tb + 256 > tend);

            // NOTE: no syncwarp needed here — step-3 reads and these writes
            // touch only the lane's OWN row (same addresses, program order).
            #pragma unroll
            for (int s = 0; s < 6; ++s) {
                float4 u;
                u.x = r[s * 4 + 0]; u.y = r[s * 4 + 1];
                u.z = r[s * 4 + 2]; u.w = r[s * 4 + 3];
                *reinterpret_cast<float4*>(sm + offR[s]) = u;
            }
            __syncwarp();   // rows complete before cross-row transposed reads

            float4* o4 = reinterpret_cast<float4*>(obase + fb);
            if (needGuard) {
                #pragma unroll
                for (int q = 0; q < 6; ++q) {
                    const int gf = fb + (q * 32 + lane) * 4;
                    float4 w = *reinterpret_cast<const float4*>(sm + offT[q]);
                    if (gf >= g0lo && gf < g0hi) o4[q * 32 + lane] = w;
                }
            } else {
                #pragma unroll
                for (int q = 0; q < 6; ++q) {
                    float4 w = *reinterpret_cast<const float4*>(sm + offT[q]);
                    o4[q * 32 + lane] = w;
                }
            }
        }
        // no trailing syncwarp needed: this tile is next written by a cp.async
        // issued one full iteration later (program order), and its smem reads
        // above complete long before that copy's smem write lands.
    }
}

extern "C" void kernel_launch(void* const* d_in, const int* in_sizes, int n_in,
                              void* d_out, int out_size) {
    (void)in_sizes; (void)n_in; (void)out_size;
    const float* in = (const float*)d_in[0];
    float* out = (float*)d_out;

    const int total_warps   = B * NCHUNK;          // 5120
    const int threads       = 128;                 // 4 warps / block
    const int warps_per_blk = threads / 32;
    const int blocks        = (total_warps + warps_per_blk - 1) / warps_per_blk;  // 1280

    char_scan_kernel<<<blocks, threads>>>(in, out);
}

// round 17
// speedup vs baseline: 1.0671x; 1.0671x over previous
#include <cuda_runtime.h>
#include <cstdint>

// Problem constants (fixed by the reference setup_inputs)
constexpr int B = 256;
constexpr int T = 30000;
constexpr int C = 3;

constexpr int L = 1000;           // output chunk length; T/L = 30 chunks
constexpr int W = 280;            // warm-up steps; (L+W) = 1280 = 5*256 exactly
constexpr int NCHUNK = T / L;     // 30

constexpr float ALPHA = 0.939f;
constexpr float CFF   = 3.0f;
constexpr float EPS   = 1e-10f;

__host__ __device__ constexpr double dpow(double a, int n) {
    double v = 1.0;
    for (int i = 0; i < n; ++i) v *= a;
    return v;
}
__device__ constexpr float APJ[8] = {   // alpha^(j+1), j = 0..7
    (float)dpow(0.939, 1), (float)dpow(0.939, 2), (float)dpow(0.939, 3), (float)dpow(0.939, 4),
    (float)dpow(0.939, 5), (float)dpow(0.939, 6), (float)dpow(0.939, 7), (float)dpow(0.939, 8)
};
__device__ constexpr float SCOEF[5] = { // alpha^(8 * 2^st), st = 0..4
    (float)dpow(0.939, 8), (float)dpow(0.939, 16), (float)dpow(0.939, 32),
    (float)dpow(0.939, 64), (float)dpow(0.939, 128)
};

#define FULLMASK 0xffffffffu

// Per-warp smem tile: 32 rows x 32 words (4 KB), double buffered.
// Row r's slot s (s=0..5, float4 granularity) lives at word
//   r*32 + sigma_r(s)*4,   sigma_r(s) = ((s + 6r) & 7) ^ ((r>>2) & 1)
// Column-Latin over any 8 consecutive rows (row pattern conflict-free) AND
// any 8 consecutive tile-float4 indices G=6r+s hit 8 distinct bank groups
// (transposed pattern conflict-free). Verified by enumeration.
constexpr int WARP_TILE_W = 32 * 32;

__device__ __forceinline__ int sigma_word(int r, int s) {
    return r * 32 + ((((s + 6 * r) & 7) ^ ((r >> 2) & 1)) << 2);
}

__global__ __launch_bounds__(128)
void char_scan_kernel(const float* __restrict__ in, float* __restrict__ out) {
    __shared__ float sm_all[4][2][WARP_TILE_W];   // 4 warps x 2 tiles x 4KB = 32KB

    const int gwarp = (blockIdx.x * blockDim.x + threadIdx.x) >> 5;
    const int lane  = threadIdx.x & 31;
    if (gwarp >= B * NCHUNK) return;

    const int wip = threadIdx.x >> 5;
    float* const tile0 = &sm_all[wip][0][0];
    float* const tile1 = &sm_all[wip][1][0];
    const uint32_t smb0 = (uint32_t)__cvta_generic_to_shared(tile0);
    const uint32_t smb1 = (uint32_t)__cvta_generic_to_shared(tile1);

    const int b  = gwarp / NCHUNK;
    const int k  = gwarp % NCHUNK;
    const int t0 = k * L;                  // first stored timestep (mult of 8)
    const int ts = (k == 0) ? 0 : t0 - W;  // first scanned timestep (mult of 8)
    const int tend = t0 + L;               // exclusive store bound

    const float* __restrict__ base  = in  + (size_t)b * T * C;
    float* __restrict__       obase = out + (size_t)b * T * C;

    // ---- hoisted swizzled smem word-offsets (constant per lane) ----
    int offT[6];                           // transposed pattern: G = 32q + lane
    #pragma unroll
    for (int q = 0; q < 6; ++q) {
        const int G = q * 32 + lane;
        offT[q] = sigma_word(G / 6, G % 6);
    }
    int offR[6];                           // own-row pattern: r = lane
    #pragma unroll
    for (int s = 0; s < 6; ++s) offR[s] = sigma_word(lane, s);

    // cross-round carries
    float carry_d[3] = {0.f, 0.f, 0.f};
    float carry_r[3];
    if (ts == 0) {
        carry_r[0] = 0.f; carry_r[1] = 0.f; carry_r[2] = 0.f;
    } else {
        carry_r[0] = base[(size_t)(ts - 1) * 3 + 0];
        carry_r[1] = base[(size_t)(ts - 1) * 3 + 1];
        carry_r[2] = base[(size_t)(ts - 1) * 3 + 2];
    }

    const int nrounds = (tend - ts + 255) >> 8;   // 256 timesteps per round
    const int g0lo = t0 * 3;     // store-valid float range [g0lo, g0hi)
    const int g0hi = tend * 3;

    // ---- cp.async issue: global round rd -> swizzled tile (transposed write) ----
    auto issue = [&](int rd, uint32_t smb) {
        const int fb = (ts + rd * 256) * 3;       // mult of 4 -> 16B aligned
        const float* p = base + fb + lane * 4;
        #pragma unroll
        for (int q = 0; q < 6; ++q) {
            const uint32_t dst = smb + (uint32_t)offT[q] * 4u;
            const float* src = p + q * 128;
            asm volatile("cp.async.cg.shared.global [%0], [%1], 16;\n"
                         :: "r"(dst), "l"(src) : "memory");
        }
        asm volatile("cp.async.commit_group;\n" ::: "memory");
    };

    issue(0, smb0);   // prologue: prefetch round 0

    for (int rd = 0; rd < nrounds; ++rd) {
        const int tb = ts + rd * 256;
        const int fb = tb * 3;
        const bool more = (rd + 1 < nrounds);
        if (more) issue(rd + 1, ((rd + 1) & 1) ? smb1 : smb0);

        // wait for round rd's tile (allow the just-issued group to stay in flight)
        if (more) asm volatile("cp.async.wait_group 1;\n" ::: "memory");
        else      asm volatile("cp.async.wait_group 0;\n" ::: "memory");
        __syncwarp();   // cross-lane visibility of cp.async'd tile

        float* const sm = (rd & 1) ? tile1 : tile0;

        // ---- read own row: 24 floats = timesteps tb+8*lane..+7, ch-major ----
        float r[24];
        #pragma unroll
        for (int s = 0; s < 6; ++s) {
            float4 u = *reinterpret_cast<const float4*>(sm + offR[s]);
            r[s * 4 + 0] = u.x; r[s * 4 + 1] = u.y;
            r[s * 4 + 2] = u.z; r[s * 4 + 3] = u.w;
        }

        #pragma unroll
        for (int c = 0; c < 3; ++c) {
            float rp = __shfl_up_sync(FULLMASK, r[21 + c], 1);
            if (lane == 0) rp = carry_r[c];

            // local serial scan over 8 steps; lane 0 folds in carry_d
            float s[8];
            float u0 = (r[c] - rp) + EPS;
            s[0] = (lane == 0) ? fmaf(ALPHA, carry_d[c], u0) : u0;
            #pragma unroll
            for (int j = 1; j < 8; ++j) {
                float uj = (r[j * 3 + c] - r[(j - 1) * 3 + c]) + EPS;
                s[j] = fmaf(ALPHA, s[j - 1], uj);
            }

            // Kogge-Stone over lane aggregates, ratio alpha^8
            float p = s[7];
            #pragma unroll
            for (int st = 0; st < 5; ++st) {
                const int dlt = 1 << st;
                float tshf = __shfl_up_sync(FULLMASK, p, dlt);
                if (lane >= dlt) p = fmaf(SCOEF[st], tshf, p);
            }

            float inc = __shfl_up_sync(FULLMASK, p, 1);
            float dprev;
            if (lane == 0) { inc = 0.f; dprev = carry_d[c]; }
            else           { dprev = inc; }

            // carries for next round (read r before in-place overwrite)
            carry_d[c] = __shfl_sync(FULLMASK, p, 31);
            carry_r[c] = __shfl_sync(FULLMASK, r[21 + c], 31);

            // fixup + characteristic, overwriting r[] in place
            #pragma unroll
            for (int j = 0; j < 8; ++j) {
                float d    = fmaf(APJ[j], inc, s[j]);
                float diff = d - dprev;
                r[j * 3 + c] = fmaf(d, d, CFF * (diff * diff));
                dprev = d;
            }
        }

        // ---- output path (skipped entirely on pure warm-up rounds) ----
        const bool doStore = (tb + 256 > t0);    // warp-uniform
        if (doStore) {
            const bool needGuard = (tb < t0) || (tb + 256 > tend);

            // No syncwarp needed before these writes: step-3 reads and this
            // writeback touch only the lane's OWN row words (same addresses,
            // program order per thread) — no cross-lane hazard.
            #pragma unroll
            for (int s = 0; s < 6; ++s) {
                float4 u;
                u.x = r[s * 4 + 0]; u.y = r[s * 4 + 1];
                u.z = r[s * 4 + 2]; u.w = r[s * 4 + 3];
                *reinterpret_cast<float4*>(sm + offR[s]) = u;
            }
            __syncwarp();   // rows complete before cross-row transposed reads

            float4* o4 = reinterpret_cast<float4*>(obase + fb);
            if (needGuard) {
                #pragma unroll
                for (int q = 0; q < 6; ++q) {
                    const int gf = fb + (q * 32 + lane) * 4;
                    float4 w = *reinterpret_cast<const float4*>(sm + offT[q]);
                    if (gf >= g0lo && gf < g0hi) o4[q * 32 + lane] = w;
                }
            } else {
                #pragma unroll
                for (int q = 0; q < 6; ++q) {
                    float4 w = *reinterpret_cast<const float4*>(sm + offT[q]);
                    o4[q * 32 + lane] = w;
                }
            }
        }
        // no trailing syncwarp needed: this tile is next written by a cp.async
        // issued one full iteration later (program order), and its smem reads
        // above complete long before that copy's smem write lands.
    }
}

extern "C" void kernel_launch(void* const* d_in, const int* in_sizes, int n_in,
                              void* d_out, int out_size) {
    (void)in_sizes; (void)n_in; (void)out_size;
    const float* in = (const float*)d_in[0];
    float* out = (float*)d_out;

    const int total_warps   = B * NCHUNK;          // 7680
    const int threads       = 128;                 // 4 warps / block
    const int warps_per_blk = threads / 32;
    const int blocks        = (total_warps + warps_per_blk - 1) / warps_per_blk;  // 1920

    char_scan_kernel<<<blocks, threads>>>(in, out);
}